// round 13
// baseline (speedup 1.0000x reference)
#include <cuda_runtime.h>
#include <math_constants.h>

// Problem constants (fixed by the bench)
#define TRAJ  8
#define EVAL  30
#define NB    2048          // trajectories
#define NG    256           // groups = NB/TRAJ
#define HALF  15            // evals per half-block
#define WM    400           // nx
#define HM    400           // ny
#define DM    64            // nz
#define VOXF  0.2f
#define INV_VOX 5.0f        // 1/0.2 exactly representable
#define NPTS  (TRAJ * EVAL) // 240 points per group
#define NBLK  (NG * 2)      // 512 blocks, 2 per group

// -------- persistent device scratch (no allocations allowed) --------
__device__ int4 g_bmin[NG];      // trunc'd voxel min per group (x,y,z,_)
__device__ int4 g_bmax[NG];      // trunc'd voxel max per group

// ticket barrier: monotonically increasing across replays -> replay-safe.
__device__ unsigned g_count = 0;

__global__ void __launch_bounds__(256, 4)
kFused(const float* __restrict__ Df,
       const float* __restrict__ Dp,
       const float* __restrict__ L,
       const float* __restrict__ sdf,
       const float* __restrict__ minb,
       const float* __restrict__ shapes,
       const int*   __restrict__ map_id,
       float*       __restrict__ out)
{
    const int g    = blockIdx.x >> 1;     // group
    const int half = blockIdx.x & 1;      // eval-half handled by this block
    const int tid  = threadIdx.x;
    const int lane = tid & 31;
    const int wrp  = tid >> 5;

    __shared__ float scoe[TRAJ][3][6];
    __shared__ float rmn[8][3], rmx[8][3];
    __shared__ int   s_red[8][3];         // cross-warp int max scratch
    __shared__ int   s_wls[3];
    __shared__ float s_org[3], s_ginv[3];
    __shared__ float s_mb[3];
    __shared__ int   s_m;
    __shared__ float s_cost[NPTS];

    if (tid == 0) s_m = __ldg(&map_id[g]);

    // phase-2 inputs hoisted (pure inputs -> legal pre-barrier):
    const int m2 = __ldg(&map_id[tid]);   // thread tid = group tid in phase 2

    __syncthreads();
    const int m = s_m;
    if (tid < 3) s_mb[tid] = __ldg(&minb[m * 3 + tid]);

    int shp2[3];
    #pragma unroll
    for (int c = 0; c < 3; c++) shp2[c] = (int)__ldg(&shapes[m2 * 3 + c]);

    // ---------------- Phase 1: coefficients ------------------------------
    if (tid < TRAJ * 3) {
        const int traj = tid / 3;
        const int c    = tid % 3;
        const int b    = g * TRAJ + traj;
        float d[6];
        #pragma unroll
        for (int s = 0; s < 3; s++) {
            d[s]     = Df[b * 9 + c * 3 + s];
            d[3 + s] = Dp[b * 9 + c * 3 + s];
        }
        #pragma unroll
        for (int j = 0; j < 6; j++) {
            float a = 0.f;
            #pragma unroll
            for (int k = 0; k < 6; k++) a += L[j * 6 + k] * d[k];
            scoe[traj][c][j] = a;
        }
    }
    if (half == 0 && tid < TRAJ) out[g * TRAJ + tid] = 0.f;
    __syncthreads();

    // ---------------- positions (registers) -------------------------------
    float px = 0.f, py = 0.f, pz = 0.f;
    const int  my_ev = tid % EVAL;
    const bool mine  = (tid < NPTS) &&
                       (my_ev >= half * HALF) && (my_ev < half * HALF + HALF);

    float mnx =  CUDART_INF_F, mny =  CUDART_INF_F, mnz =  CUDART_INF_F;
    float mxx = -CUDART_INF_F, mxy = -CUDART_INF_F, mxz = -CUDART_INF_F;

    if (tid < NPTS) {
        const int traj = tid / EVAL;
        const float t = (float)((double)(my_ev + 1) * (2.0 / 30.0));
        float tp[6];
        tp[0] = 1.f;
        #pragma unroll
        for (int k = 1; k < 6; k++) tp[k] = tp[k - 1] * t;

        float p[3];
        #pragma unroll
        for (int c = 0; c < 3; c++) {
            float a = 0.f;
            #pragma unroll
            for (int k = 0; k < 6; k++) a += tp[k] * scoe[traj][c][k];
            p[c] = a;
        }
        px = p[0]; py = p[1]; pz = p[2];
        mnx = mxx = px; mny = mxy = py; mnz = mxz = pz;
    }

    // ---- PRE-BARRIER full evaluation (window-independent!) ----------------
    // Corner-drop analysis: a dropped corner implies grid<0 or grid>=ls-1,
    // which implies |gp|>=1 -> point invalid -> cost zeroed. So for every
    // contributing point all 8 corners are in-window, and the trilinear
    // interp + exp can be evaluated entirely in the GLOBAL frame, before the
    // barrier. Self-consistent (l0p, frac, corners) from gxp=(p-mb)*5:
    // evaluation point differs from reference by ~3e-5 voxel (continuous).
    float cost_pre = 0.f;
    if (mine) {
        const float gxp = (px - s_mb[0]) * INV_VOX;
        const float gyp = (py - s_mb[1]) * INV_VOX;
        const float gzp = (pz - s_mb[2]) * INV_VOX;
        const float flx = floorf(gxp), fly = floorf(gyp), flz = floorf(gzp);
        const float fx = gxp - flx, fy = gyp - fly, fz = gzp - flz;
        const int l0x = min(max((int)flx, 0), WM - 2);
        const int l0y = min(max((int)fly, 0), HM - 2);
        const int l0z = min(max((int)flz, 0), DM - 2);

        const float* base = sdf + (size_t)m * DM * HM * WM
                          + ((size_t)l0z * HM + l0y) * WM + l0x;
        const float v000 = __ldg(base);
        const float v001 = __ldg(base + (size_t)HM * WM);
        const float v010 = __ldg(base + WM);
        const float v011 = __ldg(base + (size_t)HM * WM + WM);
        const float v100 = __ldg(base + 1);
        const float v101 = __ldg(base + (size_t)HM * WM + 1);
        const float v110 = __ldg(base + WM + 1);
        const float v111 = __ldg(base + (size_t)HM * WM + WM + 1);

        // trilinear (fixed order matching dx->dy->dz accumulation)
        const float wx0 = 1.f - fx, wy0 = 1.f - fy, wz0 = 1.f - fz;
        float acc = 0.f;
        acc += (wx0 * wy0 * wz0) * v000;
        acc += (wx0 * wy0 * fz ) * v001;
        acc += (wx0 * fy  * wz0) * v010;
        acc += (wx0 * fy  * fz ) * v011;
        acc += (fx  * wy0 * wz0) * v100;
        acc += (fx  * wy0 * fz ) * v101;
        acc += (fx  * fy  * wz0) * v110;
        acc += (fx  * fy  * fz ) * v111;

        cost_pre = __expf(-(acc - 0.5f) * (1.0f / 0.3f));
    }

    // ---------------- group min/max (butterfly) ----------------------------
    #pragma unroll
    for (int o = 16; o; o >>= 1) {
        mnx = fminf(mnx, __shfl_xor_sync(0xffffffffu, mnx, o));
        mny = fminf(mny, __shfl_xor_sync(0xffffffffu, mny, o));
        mnz = fminf(mnz, __shfl_xor_sync(0xffffffffu, mnz, o));
        mxx = fmaxf(mxx, __shfl_xor_sync(0xffffffffu, mxx, o));
        mxy = fmaxf(mxy, __shfl_xor_sync(0xffffffffu, mxy, o));
        mxz = fmaxf(mxz, __shfl_xor_sync(0xffffffffu, mxz, o));
    }
    if (lane == 0) {
        rmn[wrp][0] = mnx; rmn[wrp][1] = mny; rmn[wrp][2] = mnz;
        rmx[wrp][0] = mxx; rmx[wrp][1] = mxy; rmx[wrp][2] = mxz;
    }
    __syncthreads();

    // 6 threads publish bounds in parallel (c = tid>>1, max if tid&1)
    if (half == 0 && tid < 6) {
        const int  c     = tid >> 1;
        const bool isMax = tid & 1;
        float r = isMax ? rmx[0][c] : rmn[0][c];
        #pragma unroll
        for (int w = 1; w < 8; w++)
            r = isMax ? fmaxf(r, rmx[w][c]) : fminf(r, rmn[w][c]);
        // trunc toward zero after EXACT division (matches jnp.trunc)
        const int b = (int)__fdiv_rn(r - s_mb[c], VOXF);
        if (isMax) ((int*)&g_bmax[g])[c] = b;
        else       ((int*)&g_bmin[g])[c] = b;
    }

    // ---------------- Global ticket barrier (replay-safe) ------------------
    if (tid == 0) {
        __threadfence();
        const unsigned ticket = atomicAdd(&g_count, 1u);
        const unsigned target = (ticket / NBLK + 1u) * NBLK;
        while (*(volatile unsigned*)&g_count < target) { }
        __threadfence();
    }
    __syncthreads();

    // ---------------- Phase 2: window (shuffle reductions) -----------------
    {
        const int4 bmn = g_bmin[tid];     // LDG.128
        const int4 bmx = g_bmax[tid];     // LDG.128
        int mn[3] = { bmn.x, bmn.y, bmn.z };
        int mx[3] = { bmx.x, bmx.y, bmx.z };

        int sp[3];
        #pragma unroll
        for (int c = 0; c < 3; c++) {
            int s = mx[c] - mn[c];
            #pragma unroll
            for (int o = 16; o; o >>= 1)
                s = max(s, __shfl_xor_sync(0xffffffffu, s, o));
            sp[c] = s;
        }
        if (lane == 0) { s_red[wrp][0] = sp[0]; s_red[wrp][1] = sp[1]; s_red[wrp][2] = sp[2]; }
        __syncthreads();
        int span[3];
        #pragma unroll
        for (int c = 0; c < 3; c++) {
            int s = s_red[0][c];
            #pragma unroll
            for (int w = 1; w < 8; w++) s = max(s, s_red[w][c]);
            span[c] = s;
        }
        __syncthreads();   // protect s_red before reuse

        int lA[3], lB[3], sh[3];
        #pragma unroll
        for (int c = 0; c < 3; c++) {
            const int cc = (mn[c] + mx[c]) >> 1;      // Python floor-div by 2
            int a  = cc - (span[c] >> 1) - 5;
            int bx = cc + (span[c] >> 1) + 5;
            const int na = max(a, 0);
            bx += na - a; a = na;
            const int nb = min(bx, shp2[c]);
            a -= bx - nb; bx = nb;
            lA[c] = a; lB[c] = bx;
            int s = (a < 0) ? -a : 0;
            #pragma unroll
            for (int o = 16; o; o >>= 1)
                s = max(s, __shfl_xor_sync(0xffffffffu, s, o));
            sh[c] = s;
        }
        if (lane == 0) { s_red[wrp][0] = sh[0]; s_red[wrp][1] = sh[1]; s_red[wrp][2] = sh[2]; }
        __syncthreads();

        if (tid == g) {   // thread g holds group g's lA/lB in registers
            #pragma unroll
            for (int c = 0; c < 3; c++) {
                int s = s_red[0][c];
                #pragma unroll
                for (int w = 1; w < 8; w++) s = max(s, s_red[w][c]);
                const int a  = lA[c] + s;
                const int ls = lB[c] - a;
                s_wls[c]  = ls;
                s_org[c]  = (float)a * VOXF + s_mb[c];
                s_ginv[c] = __fdiv_rn(2.0f, (float)(ls - 1));
            }
        }
        __syncthreads();
    }

    // ---------------- Phase 3: validity mask only --------------------------
    if (mine) {
        // identical formulas to the accepted R12 validity path
        const float gx = (px - s_org[0]) * INV_VOX;
        const float gy = (py - s_org[1]) * INV_VOX;
        const float gz = (pz - s_org[2]) * INV_VOX;
        const float gpx = fmaf(gx, s_ginv[0], -1.0f);
        const float gpy = fmaf(gy, s_ginv[1], -1.0f);
        const float gpz = fmaf(gz, s_ginv[2], -1.0f);
        const bool valid = (gpx < 0.99f) && (gpx > -0.99f) &&
                           (gpy < 0.99f) && (gpy > -0.99f) &&
                           (gpz < 0.99f) && (gpz > -0.99f);
        s_cost[tid] = valid ? cost_pre : 0.f;
    }
    __syncthreads();

    // per-trajectory sum of this half's 15 evals (fixed order, deterministic)
    if (tid < TRAJ) {
        float s = 0.f;
        const int base = tid * EVAL + half * HALF;
        #pragma unroll
        for (int i = 0; i < HALF; i++) s += s_cost[base + i];
        atomicAdd(&out[g * TRAJ + tid], s * (float)(2.0 / 30.0));
    }
}

// ---------------------------------------------------------------
extern "C" void kernel_launch(void* const* d_in, const int* in_sizes, int n_in,
                              void* d_out, int out_size)
{
    const float* Df   = (const float*)d_in[0];
    const float* Dp   = (const float*)d_in[1];
    const float* L    = (const float*)d_in[2];
    const float* sdf  = (const float*)d_in[3];
    const float* minb = (const float*)d_in[4];
    const float* shp  = (const float*)d_in[5];
    const int*   mid  = (const int*)d_in[6];

    kFused<<<NBLK, 256>>>(Df, Dp, L, sdf, minb, shp, mid, (float*)d_out);
}

// round 15
// speedup vs baseline: 1.1875x; 1.1875x over previous
#include <cuda_runtime.h>
#include <math_constants.h>

// Problem constants (fixed by the bench)
#define TRAJ  8
#define EVAL  30
#define NB    2048          // trajectories
#define NG    256           // groups = NB/TRAJ
#define WM    400           // nx
#define HM    400           // ny
#define DM    64            // nz
#define VOXF  0.2f
#define INV_VOX 5.0f        // 1/0.2 exactly representable
#define NPTS  (TRAJ * EVAL) // 240 points per group

// -------- persistent device scratch (no allocations allowed) --------
__device__ int4   g_bmin[NG];          // trunc'd voxel min per group
__device__ int4   g_bmax[NG];          // trunc'd voxel max per group
__device__ float4 g_pc[NG * NPTS];     // (px, py, pz, cost_pre) per point

// ---------------------------------------------------------------
// k1: positions + window-independent cost + per-group voxel bounds.
// One block per group, 256 threads (240 active).
// ---------------------------------------------------------------
__global__ void __launch_bounds__(256, 4)
k1(const float* __restrict__ Df,
   const float* __restrict__ Dp,
   const float* __restrict__ L,
   const float* __restrict__ sdf,
   const float* __restrict__ minb,
   const int*   __restrict__ map_id)
{
    const int g    = blockIdx.x;
    const int tid  = threadIdx.x;
    const int lane = tid & 31;
    const int wrp  = tid >> 5;

    __shared__ float scoe[TRAJ][3][6];
    __shared__ float rmn[8][3], rmx[8][3];
    __shared__ float s_mb[3];
    __shared__ int   s_m;

    if (tid == 0) s_m = __ldg(&map_id[g]);
    __syncthreads();
    const int m = s_m;
    if (tid < 3) s_mb[tid] = __ldg(&minb[m * 3 + tid]);

    // coefficients
    if (tid < TRAJ * 3) {
        const int traj = tid / 3;
        const int c    = tid % 3;
        const int b    = g * TRAJ + traj;
        float d[6];
        #pragma unroll
        for (int s = 0; s < 3; s++) {
            d[s]     = Df[b * 9 + c * 3 + s];
            d[3 + s] = Dp[b * 9 + c * 3 + s];
        }
        #pragma unroll
        for (int j = 0; j < 6; j++) {
            float a = 0.f;
            #pragma unroll
            for (int k = 0; k < 6; k++) a += L[j * 6 + k] * d[k];
            scoe[traj][c][j] = a;
        }
    }
    __syncthreads();

    float px = 0.f, py = 0.f, pz = 0.f;
    float mnx =  CUDART_INF_F, mny =  CUDART_INF_F, mnz =  CUDART_INF_F;
    float mxx = -CUDART_INF_F, mxy = -CUDART_INF_F, mxz = -CUDART_INF_F;

    if (tid < NPTS) {
        const int traj = tid / EVAL;
        const int n    = tid % EVAL;
        // linspace(dt, T, 30): step == dt exactly, so t = (n+1)*dt.
        const float t = (float)((double)(n + 1) * (2.0 / 30.0));
        float tp[6];
        tp[0] = 1.f;
        #pragma unroll
        for (int k = 1; k < 6; k++) tp[k] = tp[k - 1] * t;

        float p[3];
        #pragma unroll
        for (int c = 0; c < 3; c++) {
            float a = 0.f;
            #pragma unroll
            for (int k = 0; k < 6; k++) a += tp[k] * scoe[traj][c][k];
            p[c] = a;
        }
        px = p[0]; py = p[1]; pz = p[2];
        mnx = mxx = px; mny = mxy = py; mnz = mxz = pz;
    }

    // ---- window-independent cost (R13-validated) --------------------------
    // A dropped trilinear corner implies |gp|>=1 -> point invalid -> zeroed.
    // So contributing points have all 8 corners in-window, and the interp +
    // exp can be evaluated in the GLOBAL frame (self-consistent l0/frac).
    float cost_pre = 0.f;
    if (tid < NPTS) {
        const float gxp = (px - s_mb[0]) * INV_VOX;
        const float gyp = (py - s_mb[1]) * INV_VOX;
        const float gzp = (pz - s_mb[2]) * INV_VOX;
        const float flx = floorf(gxp), fly = floorf(gyp), flz = floorf(gzp);
        const float fx = gxp - flx, fy = gyp - fly, fz = gzp - flz;
        const int l0x = min(max((int)flx, 0), WM - 2);
        const int l0y = min(max((int)fly, 0), HM - 2);
        const int l0z = min(max((int)flz, 0), DM - 2);

        const float* base = sdf + (size_t)m * DM * HM * WM
                          + ((size_t)l0z * HM + l0y) * WM + l0x;
        const float v000 = __ldg(base);
        const float v001 = __ldg(base + (size_t)HM * WM);
        const float v010 = __ldg(base + WM);
        const float v011 = __ldg(base + (size_t)HM * WM + WM);
        const float v100 = __ldg(base + 1);
        const float v101 = __ldg(base + (size_t)HM * WM + 1);
        const float v110 = __ldg(base + WM + 1);
        const float v111 = __ldg(base + (size_t)HM * WM + WM + 1);

        const float wx0 = 1.f - fx, wy0 = 1.f - fy, wz0 = 1.f - fz;
        float acc = 0.f;
        acc += (wx0 * wy0 * wz0) * v000;
        acc += (wx0 * wy0 * fz ) * v001;
        acc += (wx0 * fy  * wz0) * v010;
        acc += (wx0 * fy  * fz ) * v011;
        acc += (fx  * wy0 * wz0) * v100;
        acc += (fx  * wy0 * fz ) * v101;
        acc += (fx  * fy  * wz0) * v110;
        acc += (fx  * fy  * fz ) * v111;

        cost_pre = __expf(-(acc - 0.5f) * (1.0f / 0.3f));
        g_pc[g * NPTS + tid] = make_float4(px, py, pz, cost_pre);
    }

    // ---- group min/max + bounds -------------------------------------------
    #pragma unroll
    for (int o = 16; o; o >>= 1) {
        mnx = fminf(mnx, __shfl_xor_sync(0xffffffffu, mnx, o));
        mny = fminf(mny, __shfl_xor_sync(0xffffffffu, mny, o));
        mnz = fminf(mnz, __shfl_xor_sync(0xffffffffu, mnz, o));
        mxx = fmaxf(mxx, __shfl_xor_sync(0xffffffffu, mxx, o));
        mxy = fmaxf(mxy, __shfl_xor_sync(0xffffffffu, mxy, o));
        mxz = fmaxf(mxz, __shfl_xor_sync(0xffffffffu, mxz, o));
    }
    if (lane == 0) {
        rmn[wrp][0] = mnx; rmn[wrp][1] = mny; rmn[wrp][2] = mnz;
        rmx[wrp][0] = mxx; rmx[wrp][1] = mxy; rmx[wrp][2] = mxz;
    }
    __syncthreads();

    if (tid < 6) {   // 6 threads publish bounds in parallel
        const int  c     = tid >> 1;
        const bool isMax = tid & 1;
        float r = isMax ? rmx[0][c] : rmn[0][c];
        #pragma unroll
        for (int w = 1; w < 8; w++)
            r = isMax ? fmaxf(r, rmx[w][c]) : fminf(r, rmn[w][c]);
        // trunc toward zero after EXACT division (matches jnp.trunc)
        const int b = (int)__fdiv_rn(r - s_mb[c], VOXF);
        if (isMax) ((int*)&g_bmax[g])[c] = b;
        else       ((int*)&g_bmin[g])[c] = b;
    }
}

// ---------------------------------------------------------------
// k2: window reductions + validity mask + per-trajectory sums.
// One block per group, 256 threads. No atomics (single owner per output).
// ---------------------------------------------------------------
__global__ void __launch_bounds__(256, 4)
k2(const float* __restrict__ minb,
   const float* __restrict__ shapes,
   const int*   __restrict__ map_id,
   float*       __restrict__ out)
{
    const int g    = blockIdx.x;
    const int tid  = threadIdx.x;
    const int lane = tid & 31;
    const int wrp  = tid >> 5;

    __shared__ int   s_red[8][3];
    __shared__ int   s_wls[3];
    __shared__ float s_org[3], s_ginv[3];
    __shared__ float s_cost[NPTS];

    // thread tid handles group tid for the global reductions
    const int  m2 = __ldg(&map_id[tid]);
    int shp2[3];
    #pragma unroll
    for (int c = 0; c < 3; c++) shp2[c] = (int)__ldg(&shapes[m2 * 3 + c]);

    const int4 bmn = g_bmin[tid];
    const int4 bmx = g_bmax[tid];
    int mn[3] = { bmn.x, bmn.y, bmn.z };
    int mx[3] = { bmx.x, bmx.y, bmx.z };

    // global max span: butterfly + cross-warp smem
    int sp[3];
    #pragma unroll
    for (int c = 0; c < 3; c++) {
        int s = mx[c] - mn[c];
        #pragma unroll
        for (int o = 16; o; o >>= 1)
            s = max(s, __shfl_xor_sync(0xffffffffu, s, o));
        sp[c] = s;
    }
    if (lane == 0) { s_red[wrp][0] = sp[0]; s_red[wrp][1] = sp[1]; s_red[wrp][2] = sp[2]; }
    __syncthreads();
    int span[3];
    #pragma unroll
    for (int c = 0; c < 3; c++) {
        int s = s_red[0][c];
        #pragma unroll
        for (int w = 1; w < 8; w++) s = max(s, s_red[w][c]);
        span[c] = s;
    }
    __syncthreads();   // protect s_red before reuse

    // per-group clip, then global max shift
    int lA[3], lB[3], sh[3];
    #pragma unroll
    for (int c = 0; c < 3; c++) {
        const int cc = (mn[c] + mx[c]) >> 1;      // Python floor-div by 2
        int a  = cc - (span[c] >> 1) - 5;
        int bx = cc + (span[c] >> 1) + 5;
        const int na = max(a, 0);
        bx += na - a; a = na;
        const int nb = min(bx, shp2[c]);
        a -= bx - nb; bx = nb;
        lA[c] = a; lB[c] = bx;
        int s = (a < 0) ? -a : 0;
        #pragma unroll
        for (int o = 16; o; o >>= 1)
            s = max(s, __shfl_xor_sync(0xffffffffu, s, o));
        sh[c] = s;
    }
    if (lane == 0) { s_red[wrp][0] = sh[0]; s_red[wrp][1] = sh[1]; s_red[wrp][2] = sh[2]; }
    __syncthreads();

    if (tid == g) {   // thread g holds group g's lA/lB in registers
        const float mb0 = __ldg(&minb[m2 * 3 + 0]);
        const float mb1 = __ldg(&minb[m2 * 3 + 1]);
        const float mb2 = __ldg(&minb[m2 * 3 + 2]);
        const float mb[3] = { mb0, mb1, mb2 };
        #pragma unroll
        for (int c = 0; c < 3; c++) {
            int s = s_red[0][c];
            #pragma unroll
            for (int w = 1; w < 8; w++) s = max(s, s_red[w][c]);
            const int a  = lA[c] + s;
            const int ls = lB[c] - a;
            s_wls[c]  = ls;
            s_org[c]  = (float)a * VOXF + mb[c];
            s_ginv[c] = __fdiv_rn(2.0f, (float)(ls - 1));
        }
    }
    __syncthreads();

    // validity mask (identical formulas to accepted R12/R13 path)
    if (tid < NPTS) {
        const float4 pc = g_pc[g * NPTS + tid];
        const float gx = (pc.x - s_org[0]) * INV_VOX;
        const float gy = (pc.y - s_org[1]) * INV_VOX;
        const float gz = (pc.z - s_org[2]) * INV_VOX;
        const float gpx = fmaf(gx, s_ginv[0], -1.0f);
        const float gpy = fmaf(gy, s_ginv[1], -1.0f);
        const float gpz = fmaf(gz, s_ginv[2], -1.0f);
        const bool valid = (gpx < 0.99f) && (gpx > -0.99f) &&
                           (gpy < 0.99f) && (gpy > -0.99f) &&
                           (gpz < 0.99f) && (gpz > -0.99f);
        s_cost[tid] = valid ? pc.w : 0.f;
    }
    __syncthreads();

    // per-trajectory sum, full in-order 30-term chain (matches reference)
    if (tid < TRAJ) {
        float s = 0.f;
        const int base = tid * EVAL;
        #pragma unroll
        for (int i = 0; i < EVAL; i++) s += s_cost[base + i];
        out[g * TRAJ + tid] = s * (float)(2.0 / 30.0);
    }
}

// ---------------------------------------------------------------
extern "C" void kernel_launch(void* const* d_in, const int* in_sizes, int n_in,
                              void* d_out, int out_size)
{
    const float* Df   = (const float*)d_in[0];
    const float* Dp   = (const float*)d_in[1];
    const float* L    = (const float*)d_in[2];
    const float* sdf  = (const float*)d_in[3];
    const float* minb = (const float*)d_in[4];
    const float* shp  = (const float*)d_in[5];
    const int*   mid  = (const int*)d_in[6];

    k1<<<NG, 256>>>(Df, Dp, L, sdf, minb, mid);
    k2<<<NG, 256>>>(minb, shp, mid, (float*)d_out);
}